// round 12
// baseline (speedup 1.0000x reference)
#include <cuda_runtime.h>
#include <cuda_bf16.h>
#include <cstdint>

// Problem constants (fixed by setup_inputs)
#define SS 2000   // filtration points
#define PP 2500   // sample points
#define RR 5      // bars per point
#define NB 256    // buckets for counting sort
#define NROWS (10 * PP)        // 25000 gm rows
#define GRID_PERS 1924         // 13 CTAs x 148 SMs

// Output layout (flattened concatenation, floats):
//   bars_stack : [0, 25000)
//   gm0        : [25000, 50025000)           (R,P,2S)
//   gc0        : [50025000, 50050000)        (R,P,2)
//   gm1        : [50050000, 100050000)
//   gc1        : [100050000, 100075000)

// Bucket-sorted packed tables: {key, companion, s_as_float_bits, tol}
__device__ float4 g_px[SS];            // sorted by fx
__device__ float4 g_py[SS];            // sorted by fy
__device__ int    g_ofx[NB + 1], g_ofy[NB + 1];

// One block per axis (blockIdx.x = axis), parallel prefix scan.
__global__ void bin_kernel(const float* __restrict__ filt)
{
    __shared__ int hist[NB];
    __shared__ int scan[NB];
    __shared__ int cur[NB];
    int t = threadIdx.x;
    int axis = blockIdx.x;

    hist[t] = 0;
    __syncthreads();
    for (int s = t; s < SS; s += NB) {
        float v = filt[2 * s + axis];
        int b = min(NB - 1, max(0, (int)floorf(v * (float)NB)));
        atomicAdd(&hist[b], 1);
    }
    __syncthreads();
    // inclusive scan (Hillis-Steele)
    int v = hist[t];
    scan[t] = v;
    __syncthreads();
    #pragma unroll
    for (int ofs = 1; ofs < NB; ofs <<= 1) {
        int add = (t >= ofs) ? scan[t - ofs] : 0;
        __syncthreads();
        scan[t] += add;
        __syncthreads();
    }
    int excl = scan[t] - v;
    int* offs = axis ? g_ofy : g_ofx;
    offs[t] = excl;
    if (t == NB - 1) offs[NB] = scan[t];
    cur[t] = excl;
    __syncthreads();
    float4* tab = axis ? g_py : g_px;
    for (int s = t; s < SS; s += NB) {
        float kv = filt[2 * s + axis];
        float cv = filt[2 * s + (1 - axis)];
        int b = min(NB - 1, max(0, (int)floorf(kv * (float)NB)));
        int pos = atomicAdd(&cur[b], 1);
        // tol with the exact reference arithmetic (no FMA fusion)
        float tol = __fadd_rn(0.01f, __fmul_rn(1e-5f, fabsf(kv)));
        tab[pos] = make_float4(kv, cv, __int_as_float(s), tol);
    }
}

// Sweep the 10 (axis, shift) candidate ranges for one row.
// UNDO=false: write +/-1 into srow, return hit flag bits.
// UNDO=true : write 0 at exactly the same positions (restore zeros).
template <bool UNDO>
__device__ __forceinline__ unsigned sweep_row(
    float* srow, int warp, int lane,
    float ptx, float pty, float psum, float sc)
{
    unsigned mybits = 0u;
    for (int rid = warp; rid < 10; rid += 4) {
        int   axis = rid / 5;
        float kf   = (float)(rid % 5 - 2);
        float myp  = axis ? pty : ptx;       // line anchor for this axis
        float otp  = axis ? ptx : pty;       // companion axis anchor
        // Exact reference arithmetic (mul then add, no FMA fusion):
        float line  = __fadd_rn(__fmul_rn(kf, sc), myp);
        float lastc = __fadd_rn(__fmul_rn(2.0f, sc), otp); // last_{other axis}
        // Widened bucket range (max tol = 0.01001 < 0.0101)
        int b0 = min(NB - 1, max(0, (int)floorf((line - 0.0101f) * (float)NB)));
        int b1 = min(NB - 1, max(0, (int)floorf((line + 0.0101f) * (float)NB)));
        const int*    offs = axis ? g_ofy : g_ofx;
        const float4* tab  = axis ? g_py  : g_px;
        int lo = __ldg(&offs[b0]);
        int hi = __ldg(&offs[b1 + 1]);
        for (int i = lo + lane; i < hi; i += 32) {
            float4 e = __ldg(&tab[i]);          // {key, comp, s_bits, tol}
            bool hit = (fabsf(__fadd_rn(line, -e.x)) <= e.w)   // close?
                    && (e.y <= lastc);                          // cond gate
            if (!hit) continue;
            float fsum = __fadd_rn(e.x, e.y);                  // fx+fy (commutes)
            if (fsum == psum) continue;                        // value 0
            bool above = fsum > psum;
            int s = __float_as_int(e.z);
            if (UNDO) {
                srow[2 * s + axis] = 0.0f;
            } else {
                srow[2 * s + axis] = above ? 1.0f : -1.0f;
                mybits |= (axis ? 4u : 1u) << (above ? 0 : 1);
            }
        }
    }
    return mybits;
}

// Persistent CTAs: each block zeroes its smem row buffer ONCE, then loops
// over rows: scatter -> TMA bulk store -> undo-scatter (restore zeros).
__global__ __launch_bounds__(128) void grad_kernel(
    const float* __restrict__ bars0,
    const float* __restrict__ bars1,
    const float* __restrict__ pts,
    float* __restrict__ out)
{
    const size_t GM0 = 2ull * PP * RR;                     // 25000
    const size_t GC0 = GM0 + (size_t)RR * PP * 2 * SS;     // 50025000
    const size_t GM1 = GC0 + (size_t)RR * PP * 2;          // 50050000
    const size_t GC1 = GM1 + (size_t)RR * PP * 2 * SS;     // 100050000

    __shared__ __align__(16) float srow[2 * SS];   // 16000-byte row buffer
    __shared__ unsigned sflags;

    int t = threadIdx.x;
    int warp = t >> 5, lane = t & 31;

    // ---- one-time zero of the smem buffer ----
    float4* s4 = (float4*)srow;
    const float4 z4 = make_float4(0.f, 0.f, 0.f, 0.f);
    #pragma unroll
    for (int i = 0; i < 8; ++i) {
        int idx = t + i * 128;
        if (idx < SS / 2) s4[idx] = z4;
    }
    if (t == 0) sflags = 0u;
    __syncthreads();

    for (int row = blockIdx.x; row < NROWS; row += GRID_PERS) {
        int c = row / PP;          // combo 0..9 (p-major)
        int p = row - c * PP;
        int h = c / RR, r = c - h * RR;

        float2 pt = ((const float2*)pts)[p];
        float ptx = pt.x, pty = pt.y;
        float psum = __fadd_rn(ptx, pty);
        float bar = (h ? bars1 : bars0)[p * RR + r];
        float sc  = __fadd_rn(bar, 0.01f);             // scale = bar + GRID_RES

        // ---- scatter into the clean buffer ----
        unsigned mybits = sweep_row<false>(srow, warp, lane, ptx, pty, psum, sc);
        mybits = __reduce_or_sync(0xffffffffu, mybits);
        if (lane == 0 && mybits) atomicOr(&sflags, mybits);
        __syncthreads();

        size_t rowbase = (h == 0 ? GM0 : GM1) +
                         ((size_t)r * PP + p) * (size_t)(2 * SS);

        if (t == 0) {
            out[(size_t)h * PP * RR + (size_t)p * RR + r] = bar;   // bars_stack
            unsigned fl = sflags;
            // cx = anyUpper ? -1 : anyLower ? 1 : 0   (signs flipped vs gm)
            float cxv = (fl & 1u) ? -1.0f : ((fl & 2u) ? 1.0f : 0.0f);
            float cyv = (fl & 4u) ? -1.0f : ((fl & 8u) ? 1.0f : 0.0f);
            size_t gcb = (h == 0 ? GC0 : GC1) + ((size_t)r * PP + p) * 2;
            out[gcb]     = cxv;
            out[gcb + 1] = cyv;
            sflags = 0u;   // reset for next row (ordered by barrier below)

            // make generic smem stores visible to the async proxy
            asm volatile("fence.proxy.async.shared::cta;" ::: "memory");
            unsigned int saddr;
            asm("{ .reg .u64 tmp; cvta.to.shared.u64 tmp, %1; cvt.u32.u64 %0, tmp; }"
                : "=r"(saddr) : "l"(srow));
            asm volatile(
                "cp.async.bulk.global.shared::cta.bulk_group [%0], [%1], %2;"
                :: "l"(out + rowbase), "r"(saddr), "r"((int)(2 * SS * sizeof(float)))
                : "memory");
            asm volatile("cp.async.bulk.commit_group;" ::: "memory");
            // buffer is reused next iteration: bulk read must complete
            asm volatile("cp.async.bulk.wait_group 0;" ::: "memory");
        }
        __syncthreads();   // TMA done; safe to modify srow again

        // ---- undo-scatter: restore zeros at exactly the dirtied words ----
        sweep_row<true>(srow, warp, lane, ptx, pty, psum, sc);
        __syncthreads();   // clean buffer (and sflags=0) visible to next row
    }
}

extern "C" void kernel_launch(void* const* d_in, const int* in_sizes, int n_in,
                              void* d_out, int out_size)
{
    (void)in_sizes; (void)n_in; (void)out_size;
    const float* filtration = (const float*)d_in[0];   // (S,2)
    const float* bars0      = (const float*)d_in[1];   // (P,R)
    const float* bars1      = (const float*)d_in[2];   // (P,R)
    const float* pts        = (const float*)d_in[3];   // (P,2)
    float* out = (float*)d_out;

    bin_kernel<<<2, NB>>>(filtration);
    grad_kernel<<<GRID_PERS, 128>>>(bars0, bars1, pts, out);
}

// round 13
// speedup vs baseline: 1.1181x; 1.1181x over previous
#include <cuda_runtime.h>
#include <cuda_bf16.h>
#include <cstdint>

// Problem constants (fixed by setup_inputs)
#define SS 2000   // filtration points
#define PP 2500   // sample points
#define RR 5      // bars per point
#define NB 256    // buckets for counting sort
#define NROWS (10 * PP)        // 25000 gm rows
#define GRID_PERS 1036         // 7 CTAs x 148 SMs (32KB smem each)

// Output layout (flattened concatenation, floats):
//   bars_stack : [0, 25000)
//   gm0        : [25000, 50025000)           (R,P,2S)
//   gc0        : [50025000, 50050000)        (R,P,2)
//   gm1        : [50050000, 100050000)
//   gc1        : [100050000, 100075000)

// Bucket-sorted packed tables: {key, companion, s_as_float_bits, tol}
__device__ float4 g_px[SS];            // sorted by fx
__device__ float4 g_py[SS];            // sorted by fy
__device__ int    g_ofx[NB + 1], g_ofy[NB + 1];

// One block per axis (blockIdx.x = axis), parallel prefix scan.
__global__ void bin_kernel(const float* __restrict__ filt)
{
    __shared__ int hist[NB];
    __shared__ int scan[NB];
    __shared__ int cur[NB];
    int t = threadIdx.x;
    int axis = blockIdx.x;

    hist[t] = 0;
    __syncthreads();
    for (int s = t; s < SS; s += NB) {
        float v = filt[2 * s + axis];
        int b = min(NB - 1, max(0, (int)floorf(v * (float)NB)));
        atomicAdd(&hist[b], 1);
    }
    __syncthreads();
    // inclusive scan (Hillis-Steele)
    int v = hist[t];
    scan[t] = v;
    __syncthreads();
    #pragma unroll
    for (int ofs = 1; ofs < NB; ofs <<= 1) {
        int add = (t >= ofs) ? scan[t - ofs] : 0;
        __syncthreads();
        scan[t] += add;
        __syncthreads();
    }
    int excl = scan[t] - v;
    int* offs = axis ? g_ofy : g_ofx;
    offs[t] = excl;
    if (t == NB - 1) offs[NB] = scan[t];
    cur[t] = excl;
    __syncthreads();
    float4* tab = axis ? g_py : g_px;
    for (int s = t; s < SS; s += NB) {
        float kv = filt[2 * s + axis];
        float cv = filt[2 * s + (1 - axis)];
        int b = min(NB - 1, max(0, (int)floorf(kv * (float)NB)));
        int pos = atomicAdd(&cur[b], 1);
        // tol with the exact reference arithmetic (no FMA fusion)
        float tol = __fadd_rn(0.01f, __fmul_rn(1e-5f, fabsf(kv)));
        tab[pos] = make_float4(kv, cv, __int_as_float(s), tol);
    }
}

// Sweep the 10 (axis, shift) candidate ranges for one row.
// UNDO=false: write +/-1 into srow, return hit flag bits.
// UNDO=true : write 0 at exactly the same positions (restore zeros).
template <bool UNDO>
__device__ __forceinline__ unsigned sweep_row(
    float* srow, int warp, int lane,
    float ptx, float pty, float psum, float sc)
{
    unsigned mybits = 0u;
    for (int rid = warp; rid < 10; rid += 4) {
        int   axis = rid / 5;
        float kf   = (float)(rid % 5 - 2);
        float myp  = axis ? pty : ptx;       // line anchor for this axis
        float otp  = axis ? ptx : pty;       // companion axis anchor
        // Exact reference arithmetic (mul then add, no FMA fusion):
        float line  = __fadd_rn(__fmul_rn(kf, sc), myp);
        float lastc = __fadd_rn(__fmul_rn(2.0f, sc), otp); // last_{other axis}
        // Widened bucket range (max tol = 0.01001 < 0.0101)
        int b0 = min(NB - 1, max(0, (int)floorf((line - 0.0101f) * (float)NB)));
        int b1 = min(NB - 1, max(0, (int)floorf((line + 0.0101f) * (float)NB)));
        const int*    offs = axis ? g_ofy : g_ofx;
        const float4* tab  = axis ? g_py  : g_px;
        int lo = __ldg(&offs[b0]);
        int hi = __ldg(&offs[b1 + 1]);
        for (int i = lo + lane; i < hi; i += 32) {
            float4 e = __ldg(&tab[i]);          // {key, comp, s_bits, tol}
            bool hit = (fabsf(__fadd_rn(line, -e.x)) <= e.w)   // close?
                    && (e.y <= lastc);                          // cond gate
            if (!hit) continue;
            float fsum = __fadd_rn(e.x, e.y);                  // fx+fy (commutes)
            if (fsum == psum) continue;                        // value 0
            bool above = fsum > psum;
            int s = __float_as_int(e.z);
            if (UNDO) {
                srow[2 * s + axis] = 0.0f;
            } else {
                srow[2 * s + axis] = above ? 1.0f : -1.0f;
                mybits |= (axis ? 4u : 1u) << (above ? 0 : 1);
            }
        }
    }
    return mybits;
}

// Persistent CTAs with DOUBLE-BUFFERED smem rows:
//   row i uses buffer i&1; its TMA store is waited on only at row i+2,
//   after a full row of compute — the wait is effectively free.
__global__ __launch_bounds__(128) void grad_kernel(
    const float* __restrict__ bars0,
    const float* __restrict__ bars1,
    const float* __restrict__ pts,
    float* __restrict__ out)
{
    const size_t GM0 = 2ull * PP * RR;                     // 25000
    const size_t GC0 = GM0 + (size_t)RR * PP * 2 * SS;     // 50025000
    const size_t GM1 = GC0 + (size_t)RR * PP * 2;          // 50050000
    const size_t GC1 = GM1 + (size_t)RR * PP * 2 * SS;     // 100050000

    __shared__ __align__(16) float srow[2][2 * SS];  // 2 x 16000-byte buffers
    __shared__ unsigned sflags;

    int t = threadIdx.x;
    int warp = t >> 5, lane = t & 31;

    // ---- one-time zero of both buffers ----
    float4* s40 = (float4*)srow[0];
    float4* s41 = (float4*)srow[1];
    const float4 z4 = make_float4(0.f, 0.f, 0.f, 0.f);
    #pragma unroll
    for (int i = 0; i < 8; ++i) {
        int idx = t + i * 128;
        if (idx < SS / 2) { s40[idx] = z4; s41[idx] = z4; }
    }
    if (t == 0) sflags = 0u;
    __syncthreads();

    int iter = 0;
    bool issued = false;
    for (int row = blockIdx.x; row < NROWS; row += GRID_PERS, ++iter) {
        int bsel = iter & 1;
        float* buf = srow[bsel];

        // 1) ensure TMA from iteration iter-2 (same buffer) is done
        if (t == 0 && iter >= 2)
            asm volatile("cp.async.bulk.wait_group 1;" ::: "memory");
        __syncthreads();

        // 2) undo the scatter from iteration iter-2 (restore zeros)
        if (iter >= 2) {
            int orow = row - 2 * GRID_PERS;
            int oc = orow / PP;
            int op = orow - oc * PP;
            int oh = oc / RR, orr = oc - oh * RR;
            float2 opt = ((const float2*)pts)[op];
            float opsum = __fadd_rn(opt.x, opt.y);
            float obar = (oh ? bars1 : bars0)[op * RR + orr];
            float osc  = __fadd_rn(obar, 0.01f);
            sweep_row<true>(buf, warp, lane, opt.x, opt.y, opsum, osc);
        }
        __syncthreads();   // undo ordered before new scatter (may share words)

        // 3) scatter this row into the clean buffer
        int c = row / PP;          // combo 0..9 (p-major)
        int p = row - c * PP;
        int h = c / RR, r = c - h * RR;
        float2 pt = ((const float2*)pts)[p];
        float ptx = pt.x, pty = pt.y;
        float psum = __fadd_rn(ptx, pty);
        float bar = (h ? bars1 : bars0)[p * RR + r];
        float sc  = __fadd_rn(bar, 0.01f);             // scale = bar + GRID_RES

        unsigned mybits = sweep_row<false>(buf, warp, lane, ptx, pty, psum, sc);
        mybits = __reduce_or_sync(0xffffffffu, mybits);
        if (lane == 0 && mybits) atomicOr(&sflags, mybits);
        __syncthreads();

        // 4) t0: scalar outputs + async TMA store (NO wait here)
        size_t rowbase = (h == 0 ? GM0 : GM1) +
                         ((size_t)r * PP + p) * (size_t)(2 * SS);
        if (t == 0) {
            out[(size_t)h * PP * RR + (size_t)p * RR + r] = bar;   // bars_stack
            unsigned fl = sflags;
            // cx = anyUpper ? -1 : anyLower ? 1 : 0   (signs flipped vs gm)
            float cxv = (fl & 1u) ? -1.0f : ((fl & 2u) ? 1.0f : 0.0f);
            float cyv = (fl & 4u) ? -1.0f : ((fl & 8u) ? 1.0f : 0.0f);
            size_t gcb = (h == 0 ? GC0 : GC1) + ((size_t)r * PP + p) * 2;
            out[gcb]     = cxv;
            out[gcb + 1] = cyv;
            sflags = 0u;   // next scatter's atomicOr is after next top barrier

            // make generic smem stores visible to the async proxy
            asm volatile("fence.proxy.async.shared::cta;" ::: "memory");
            unsigned int saddr;
            asm("{ .reg .u64 tmp; cvta.to.shared.u64 tmp, %1; cvt.u32.u64 %0, tmp; }"
                : "=r"(saddr) : "l"(buf));
            asm volatile(
                "cp.async.bulk.global.shared::cta.bulk_group [%0], [%1], %2;"
                :: "l"(out + rowbase), "r"(saddr), "r"((int)(2 * SS * sizeof(float)))
                : "memory");
            asm volatile("cp.async.bulk.commit_group;" ::: "memory");
        }
        issued = true;
    }

    // tail: all outstanding TMA reads of smem must finish before block exit
    if (t == 0 && issued)
        asm volatile("cp.async.bulk.wait_group 0;" ::: "memory");
    __syncthreads();
}

extern "C" void kernel_launch(void* const* d_in, const int* in_sizes, int n_in,
                              void* d_out, int out_size)
{
    (void)in_sizes; (void)n_in; (void)out_size;
    const float* filtration = (const float*)d_in[0];   // (S,2)
    const float* bars0      = (const float*)d_in[1];   // (P,R)
    const float* bars1      = (const float*)d_in[2];   // (P,R)
    const float* pts        = (const float*)d_in[3];   // (P,2)
    float* out = (float*)d_out;

    bin_kernel<<<2, NB>>>(filtration);
    grad_kernel<<<GRID_PERS, 128>>>(bars0, bars1, pts, out);
}

// round 14
// speedup vs baseline: 1.8529x; 1.6572x over previous
#include <cuda_runtime.h>
#include <cuda_bf16.h>
#include <cstdint>

// Problem constants (fixed by setup_inputs)
#define SS 2000   // filtration points
#define PP 2500   // sample points
#define RR 5      // bars per point
#define NB 256    // buckets for counting sort

// Output layout (flattened concatenation, floats):
//   bars_stack : [0, 25000)
//   gm0        : [25000, 50025000)           (R,P,2S)
//   gc0        : [50025000, 50050000)        (R,P,2)
//   gm1        : [50050000, 100050000)
//   gc1        : [100050000, 100075000)

// Bucket-sorted packed tables: {key, companion, s_as_float_bits, tol}
__device__ float4 g_px[SS];            // sorted by fx
__device__ float4 g_py[SS];            // sorted by fy
__device__ int    g_ofx[NB + 1], g_ofy[NB + 1];

// One block per axis (blockIdx.x = axis), parallel prefix scan.
__global__ void bin_kernel(const float* __restrict__ filt)
{
    __shared__ int hist[NB];
    __shared__ int scan[NB];
    __shared__ int cur[NB];
    int t = threadIdx.x;
    int axis = blockIdx.x;

    hist[t] = 0;
    __syncthreads();
    for (int s = t; s < SS; s += NB) {
        float v = filt[2 * s + axis];
        int b = min(NB - 1, max(0, (int)floorf(v * (float)NB)));
        atomicAdd(&hist[b], 1);
    }
    __syncthreads();
    // inclusive scan (Hillis-Steele)
    int v = hist[t];
    scan[t] = v;
    __syncthreads();
    #pragma unroll
    for (int ofs = 1; ofs < NB; ofs <<= 1) {
        int add = (t >= ofs) ? scan[t - ofs] : 0;
        __syncthreads();
        scan[t] += add;
        __syncthreads();
    }
    int excl = scan[t] - v;
    int* offs = axis ? g_ofy : g_ofx;
    offs[t] = excl;
    if (t == NB - 1) offs[NB] = scan[t];
    cur[t] = excl;
    __syncthreads();
    float4* tab = axis ? g_py : g_px;
    for (int s = t; s < SS; s += NB) {
        float kv = filt[2 * s + axis];
        float cv = filt[2 * s + (1 - axis)];
        int b = min(NB - 1, max(0, (int)floorf(kv * (float)NB)));
        int pos = atomicAdd(&cur[b], 1);
        // tol with the exact reference arithmetic (no FMA fusion)
        float tol = __fadd_rn(0.01f, __fmul_rn(1e-5f, fabsf(kv)));
        tab[pos] = make_float4(kv, cv, __int_as_float(s), tol);
    }
}

// One (h,r,p) row per block, 128 threads = 4 warps.
// Row assembled in SMEM; written to GMEM with ONE bulk-async (TMA) copy.
// PDL secondary: the table-independent zero phase overlaps bin_kernel;
// cudaGridDependencySynchronize() gates only the scatter phase.
__global__ __launch_bounds__(128) void grad_kernel(
    const float* __restrict__ bars0,
    const float* __restrict__ bars1,
    const float* __restrict__ pts,
    float* __restrict__ out)
{
    const size_t GM0 = 2ull * PP * RR;                     // 25000
    const size_t GC0 = GM0 + (size_t)RR * PP * 2 * SS;     // 50025000
    const size_t GM1 = GC0 + (size_t)RR * PP * 2;          // 50050000
    const size_t GC1 = GM1 + (size_t)RR * PP * 2 * SS;     // 100050000

    __shared__ __align__(16) float srow[2 * SS];   // 16000-byte row buffer
    __shared__ unsigned sflags;

    int b = blockIdx.x;
    int c = b / PP;            // combo 0..9 (p-major: adjacent blocks = adjacent rows)
    int p = b - c * PP;
    int h = c / RR, r = c - h * RR;
    int t = threadIdx.x;
    int warp = t >> 5, lane = t & 31;

    float2 pt = ((const float2*)pts)[p];
    float ptx = pt.x, pty = pt.y;
    float psum = __fadd_rn(ptx, pty);

    float bar = (h ? bars1 : bars0)[p * RR + r];
    float sc  = __fadd_rn(bar, 0.01f);                  // scale = bar + GRID_RES

    if (t == 0) {
        sflags = 0u;
        out[(size_t)h * PP * RR + (size_t)p * RR + r] = bar;   // bars_stack
    }

    // ---- Phase 1: zero the smem row (independent of bin tables) ----
    float4* s4 = (float4*)srow;
    const float4 z4 = make_float4(0.f, 0.f, 0.f, 0.f);
    #pragma unroll
    for (int i = 0; i < 8; ++i) {
        int idx = t + i * 128;
        if (idx < SS / 2) s4[idx] = z4;
    }

    // Wait for bin_kernel (PDL dependency) before touching tables.
    cudaGridDependencySynchronize();
    __syncthreads();

    // ---- Phase 2: warp-owned sparse scatter into smem ----
    unsigned mybits = 0u;
    for (int rid = warp; rid < 10; rid += 4) {
        int   axis = rid / 5;
        float kf   = (float)(rid % 5 - 2);
        float myp  = axis ? pty : ptx;       // line anchor for this axis
        float otp  = axis ? ptx : pty;       // companion axis anchor
        // Exact reference arithmetic (mul then add, no FMA fusion):
        float line  = __fadd_rn(__fmul_rn(kf, sc), myp);
        float lastc = __fadd_rn(__fmul_rn(2.0f, sc), otp); // last_{other axis}
        // Widened bucket range (max tol = 0.01001 < 0.0101)
        int b0 = min(NB - 1, max(0, (int)floorf((line - 0.0101f) * (float)NB)));
        int b1 = min(NB - 1, max(0, (int)floorf((line + 0.0101f) * (float)NB)));
        const int*    offs = axis ? g_ofy : g_ofx;
        const float4* tab  = axis ? g_py  : g_px;
        int lo = __ldg(&offs[b0]);
        int hi = __ldg(&offs[b1 + 1]);
        for (int i = lo + lane; i < hi; i += 32) {
            float4 e = __ldg(&tab[i]);          // {key, comp, s_bits, tol}
            bool hit = (fabsf(__fadd_rn(line, -e.x)) <= e.w)   // close?
                    && (e.y <= lastc);                          // cond gate
            if (!hit) continue;
            float fsum = __fadd_rn(e.x, e.y);                  // fx+fy (commutes)
            if (fsum == psum) continue;                        // value 0
            bool above = fsum > psum;
            int s = __float_as_int(e.z);
            srow[2 * s + axis] = above ? 1.0f : -1.0f;
            mybits |= (axis ? 4u : 1u) << (above ? 0 : 1);
        }
    }
    mybits = __reduce_or_sync(0xffffffffu, mybits);
    if (lane == 0 && mybits) atomicOr(&sflags, mybits);
    __syncthreads();

    // ---- Phase 3: ONE bulk-async store smem -> gmem (off the L1 path) ----
    size_t rowbase = (h == 0 ? GM0 : GM1) +
                     ((size_t)r * PP + p) * (size_t)(2 * SS);

    if (t == 0) {
        unsigned fl = sflags;
        // cx = anyUpper ? -1 : anyLower ? 1 : 0   (signs flipped vs gm)
        float cxv = (fl & 1u) ? -1.0f : ((fl & 2u) ? 1.0f : 0.0f);
        float cyv = (fl & 4u) ? -1.0f : ((fl & 8u) ? 1.0f : 0.0f);
        size_t gcb = (h == 0 ? GC0 : GC1) + ((size_t)r * PP + p) * 2;
        out[gcb]     = cxv;
        out[gcb + 1] = cyv;

        // make generic smem stores visible to the async proxy
        asm volatile("fence.proxy.async.shared::cta;" ::: "memory");
        unsigned int saddr;
        asm("{ .reg .u64 tmp; cvta.to.shared.u64 tmp, %1; cvt.u32.u64 %0, tmp; }"
            : "=r"(saddr) : "l"(srow));
        asm volatile(
            "cp.async.bulk.global.shared::cta.bulk_group [%0], [%1], %2;"
            :: "l"(out + rowbase), "r"(saddr), "r"((int)(2 * SS * sizeof(float)))
            : "memory");
        asm volatile("cp.async.bulk.commit_group;" ::: "memory");
        // must not release smem until the bulk read completes
        asm volatile("cp.async.bulk.wait_group 0;" ::: "memory");
    }
}

extern "C" void kernel_launch(void* const* d_in, const int* in_sizes, int n_in,
                              void* d_out, int out_size)
{
    (void)in_sizes; (void)n_in; (void)out_size;
    const float* filtration = (const float*)d_in[0];   // (S,2)
    const float* bars0      = (const float*)d_in[1];   // (P,R)
    const float* bars1      = (const float*)d_in[2];   // (P,R)
    const float* pts        = (const float*)d_in[3];   // (P,2)
    float* out = (float*)d_out;

    bin_kernel<<<2, NB>>>(filtration);

    // PDL launch: grad may start while bin_kernel runs; the grid dependency
    // sync inside grad gates only the table-dependent scatter phase.
    cudaLaunchConfig_t cfg = {};
    cfg.gridDim  = dim3(10 * PP);
    cfg.blockDim = dim3(128);
    cfg.dynamicSmemBytes = 0;
    cfg.stream = 0;
    cudaLaunchAttribute attrs[1];
    attrs[0].id = cudaLaunchAttributeProgrammaticStreamSerialization;
    attrs[0].val.programmaticStreamSerializationAllowed = 1;
    cfg.attrs = attrs;
    cfg.numAttrs = 1;
    cudaLaunchKernelEx(&cfg, grad_kernel, bars0, bars1, pts, out);
}

// round 16
// speedup vs baseline: 1.8606x; 1.0042x over previous
#include <cuda_runtime.h>
#include <cuda_bf16.h>
#include <cstdint>

// Problem constants (fixed by setup_inputs)
#define SS 2000   // filtration points
#define PP 2500   // sample points
#define RR 5      // bars per point
#define NB 256    // buckets for counting sort

// Output layout (flattened concatenation, floats):
//   bars_stack : [0, 25000)
//   gm0        : [25000, 50025000)           (R,P,2S)
//   gc0        : [50025000, 50050000)        (R,P,2)
//   gm1        : [50050000, 100050000)
//   gc1        : [100050000, 100075000)

// Bucket-sorted packed tables: {key, companion, s_as_float_bits, tol}
__device__ float4 g_px[SS];            // sorted by fx
__device__ float4 g_py[SS];            // sorted by fy
__device__ int    g_ofx[NB + 1], g_ofy[NB + 1];

// One block per axis (blockIdx.x = axis), parallel prefix scan.
__global__ void bin_kernel(const float* __restrict__ filt)
{
    __shared__ int hist[NB];
    __shared__ int scan[NB];
    __shared__ int cur[NB];
    int t = threadIdx.x;
    int axis = blockIdx.x;

    hist[t] = 0;
    __syncthreads();
    for (int s = t; s < SS; s += NB) {
        float v = filt[2 * s + axis];
        int b = min(NB - 1, max(0, (int)floorf(v * (float)NB)));
        atomicAdd(&hist[b], 1);
    }
    __syncthreads();
    // inclusive scan (Hillis-Steele)
    int v = hist[t];
    scan[t] = v;
    __syncthreads();
    #pragma unroll
    for (int ofs = 1; ofs < NB; ofs <<= 1) {
        int add = (t >= ofs) ? scan[t - ofs] : 0;
        __syncthreads();
        scan[t] += add;
        __syncthreads();
    }
    int excl = scan[t] - v;
    int* offs = axis ? g_ofy : g_ofx;
    offs[t] = excl;
    if (t == NB - 1) offs[NB] = scan[t];
    cur[t] = excl;
    __syncthreads();
    float4* tab = axis ? g_py : g_px;
    for (int s = t; s < SS; s += NB) {
        float kv = filt[2 * s + axis];
        float cv = filt[2 * s + (1 - axis)];
        int b = min(NB - 1, max(0, (int)floorf(kv * (float)NB)));
        int pos = atomicAdd(&cur[b], 1);
        // tol with the exact reference arithmetic (no FMA fusion)
        float tol = __fadd_rn(0.01f, __fmul_rn(1e-5f, fabsf(kv)));
        tab[pos] = make_float4(kv, cv, __int_as_float(s), tol);
    }
}

// One (h,r,p) row per block, 128 threads = 4 warps.
// Row assembled in SMEM; written to GMEM with ONE bulk-async (TMA) copy.
// Block tail waits only for the TMA *read* of smem (wait_group.read), not
// for the global write to land — smem recycles immediately.
__global__ __launch_bounds__(128) void grad_kernel(
    const float* __restrict__ bars0,
    const float* __restrict__ bars1,
    const float* __restrict__ pts,
    float* __restrict__ out)
{
    const size_t GM0 = 2ull * PP * RR;                     // 25000
    const size_t GC0 = GM0 + (size_t)RR * PP * 2 * SS;     // 50025000
    const size_t GM1 = GC0 + (size_t)RR * PP * 2;          // 50050000
    const size_t GC1 = GM1 + (size_t)RR * PP * 2 * SS;     // 100050000

    __shared__ __align__(16) float srow[2 * SS];   // 16000-byte row buffer
    __shared__ unsigned sflags;

    int b = blockIdx.x;
    int c = b / PP;            // combo 0..9 (p-major: adjacent blocks = adjacent rows)
    int p = b - c * PP;
    int h = c / RR, r = c - h * RR;
    int t = threadIdx.x;
    int warp = t >> 5, lane = t & 31;

    float2 pt = ((const float2*)pts)[p];
    float ptx = pt.x, pty = pt.y;
    float psum = __fadd_rn(ptx, pty);

    float bar = (h ? bars1 : bars0)[p * RR + r];
    float sc  = __fadd_rn(bar, 0.01f);                  // scale = bar + GRID_RES

    if (t == 0) {
        sflags = 0u;
        out[(size_t)h * PP * RR + (size_t)p * RR + r] = bar;   // bars_stack
    }

    // ---- Phase 1: zero the smem row ----
    float4* s4 = (float4*)srow;
    const float4 z4 = make_float4(0.f, 0.f, 0.f, 0.f);
    #pragma unroll
    for (int i = 0; i < 8; ++i) {
        int idx = t + i * 128;
        if (idx < SS / 2) s4[idx] = z4;
    }
    __syncthreads();

    // ---- Phase 2: warp-owned sparse scatter into smem ----
    unsigned mybits = 0u;
    for (int rid = warp; rid < 10; rid += 4) {
        int   axis = rid / 5;
        float kf   = (float)(rid % 5 - 2);
        float myp  = axis ? pty : ptx;       // line anchor for this axis
        float otp  = axis ? ptx : pty;       // companion axis anchor
        // Exact reference arithmetic (mul then add, no FMA fusion):
        float line  = __fadd_rn(__fmul_rn(kf, sc), myp);
        float lastc = __fadd_rn(__fmul_rn(2.0f, sc), otp); // last_{other axis}
        // Widened bucket range (max tol = 0.01001 < 0.0101)
        int b0 = min(NB - 1, max(0, (int)floorf((line - 0.0101f) * (float)NB)));
        int b1 = min(NB - 1, max(0, (int)floorf((line + 0.0101f) * (float)NB)));
        const int*    offs = axis ? g_ofy : g_ofx;
        const float4* tab  = axis ? g_py  : g_px;
        int lo = __ldg(&offs[b0]);
        int hi = __ldg(&offs[b1 + 1]);
        for (int i = lo + lane; i < hi; i += 32) {
            float4 e = __ldg(&tab[i]);          // {key, comp, s_bits, tol}
            bool hit = (fabsf(__fadd_rn(line, -e.x)) <= e.w)   // close?
                    && (e.y <= lastc);                          // cond gate
            if (!hit) continue;
            float fsum = __fadd_rn(e.x, e.y);                  // fx+fy (commutes)
            if (fsum == psum) continue;                        // value 0
            bool above = fsum > psum;
            int s = __float_as_int(e.z);
            srow[2 * s + axis] = above ? 1.0f : -1.0f;
            mybits |= (axis ? 4u : 1u) << (above ? 0 : 1);
        }
    }
    mybits = __reduce_or_sync(0xffffffffu, mybits);
    if (lane == 0 && mybits) atomicOr(&sflags, mybits);
    __syncthreads();

    // ---- Phase 3: ONE bulk-async store smem -> gmem ----
    size_t rowbase = (h == 0 ? GM0 : GM1) +
                     ((size_t)r * PP + p) * (size_t)(2 * SS);

    if (t == 0) {
        // make generic smem stores visible to the async proxy, issue ASAP
        asm volatile("fence.proxy.async.shared::cta;" ::: "memory");
        unsigned int saddr;
        asm("{ .reg .u64 tmp; cvta.to.shared.u64 tmp, %1; cvt.u32.u64 %0, tmp; }"
            : "=r"(saddr) : "l"(srow));
        asm volatile(
            "cp.async.bulk.global.shared::cta.bulk_group [%0], [%1], %2;"
            :: "l"(out + rowbase), "r"(saddr), "r"((int)(2 * SS * sizeof(float)))
            : "memory");
        asm volatile("cp.async.bulk.commit_group;" ::: "memory");

        // scalar outputs overlap the bulk read
        unsigned fl = sflags;
        // cx = anyUpper ? -1 : anyLower ? 1 : 0   (signs flipped vs gm)
        float cxv = (fl & 1u) ? -1.0f : ((fl & 2u) ? 1.0f : 0.0f);
        float cyv = (fl & 4u) ? -1.0f : ((fl & 8u) ? 1.0f : 0.0f);
        size_t gcb = (h == 0 ? GC0 : GC1) + ((size_t)r * PP + p) * 2;
        out[gcb]     = cxv;
        out[gcb + 1] = cyv;

        // wait only until the bulk op has finished READING smem; the global
        // write drains asynchronously after block exit (CUTLASS idiom).
        asm volatile("cp.async.bulk.wait_group.read 0;" ::: "memory");
    }
}

extern "C" void kernel_launch(void* const* d_in, const int* in_sizes, int n_in,
                              void* d_out, int out_size)
{
    (void)in_sizes; (void)n_in; (void)out_size;
    const float* filtration = (const float*)d_in[0];   // (S,2)
    const float* bars0      = (const float*)d_in[1];   // (P,R)
    const float* bars1      = (const float*)d_in[2];   // (P,R)
    const float* pts        = (const float*)d_in[3];   // (P,2)
    float* out = (float*)d_out;

    bin_kernel<<<2, NB>>>(filtration);
    grad_kernel<<<10 * PP, 128>>>(bars0, bars1, pts, out);
}